// round 10
// baseline (speedup 1.0000x reference)
#include <cuda_runtime.h>
#include <cstdint>

#define B_ 64
#define T_ 1024
#define I_ 256
#define H_ 512

typedef unsigned long long u64;

// ---------------- packed f32x2 helpers (sm_103a) ----------------
__device__ __forceinline__ u64 pack2(float lo, float hi) {
    u64 r; asm("mov.b64 %0, {%1, %2};" : "=l"(r) : "f"(lo), "f"(hi)); return r;
}
__device__ __forceinline__ u64 fma2(u64 a, u64 b, u64 c) {
    u64 d; asm("fma.rn.f32x2 %0, %1, %2, %3;" : "=l"(d) : "l"(a), "l"(b), "l"(c)); return d;
}
__device__ __forceinline__ u64 add2(u64 a, u64 b) {
    u64 d; asm("add.rn.f32x2 %0, %1, %2;" : "=l"(d) : "l"(a), "l"(b)); return d;
}
__device__ __forceinline__ float2 unpack2(u64 v) {
    float2 r; asm("mov.b64 {%0, %1}, %2;" : "=f"(r.x), "=f"(r.y) : "l"(v)); return r;
}

// ---------------- static device scratch ----------------
// Projections stored transposed: [t][j][b]  -> index (t*H_ + j)*B_ + b
__device__ float g_xz[(size_t)T_ * H_ * B_];
__device__ float g_xr[(size_t)T_ * H_ * B_];
__device__ float g_xh[(size_t)T_ * H_ * B_];
// Hidden state double buffer + r*h exchange buffer, layout [b][j]
__device__ float g_h[2][B_ * H_];
__device__ float g_rh[B_ * H_];
// Per-batch-group barrier: 4 slots, 128B apart; zero-init; gen monotone (replay-safe).
struct __align__(128) BarSlot { unsigned count; unsigned gen; unsigned pad[30]; };
__device__ BarSlot g_bar[4];

// ---------------- per-batch-group barrier, scoped release/acquire ----------
__device__ __forceinline__ void group_sync_(int bg) {
    __syncthreads();
    if (threadIdx.x == 0) {
        unsigned* cnt  = &g_bar[bg].count;
        unsigned* genp = &g_bar[bg].gen;
        unsigned g0, old, v;
        asm volatile("ld.acquire.gpu.u32 %0, [%1];" : "=r"(g0) : "l"(genp) : "memory");
        asm volatile("atom.release.gpu.add.u32 %0, [%1], %2;"
                     : "=r"(old) : "l"(cnt), "r"(1u) : "memory");
        if (old == 31u) {
            asm volatile("st.relaxed.gpu.u32 [%0], %1;" :: "l"(cnt), "r"(0u) : "memory");
            asm volatile("st.release.gpu.u32 [%0], %1;" :: "l"(genp), "r"(g0 + 1u) : "memory");
        } else {
            do {
                asm volatile("ld.acquire.gpu.u32 %0, [%1];" : "=r"(v) : "l"(genp) : "memory");
            } while (v == g0);
        }
    }
    __syncthreads();
}

// =================================================================================
// Projection GEMM (unchanged from round 8)
// =================================================================================
__global__ __launch_bounds__(256) void gru_proj_kernel(
    const float* __restrict__ xs,
    const float* __restrict__ Wz, const float* __restrict__ Wr, const float* __restrict__ Wh,
    const float* __restrict__ bz, const float* __restrict__ br, const float* __restrict__ bh)
{
    __shared__ float As[8 * 132];
    __shared__ float Bs[8 * 132];

    const int g = blockIdx.z;
    const float* W    = (g == 0) ? Wz : (g == 1) ? Wr : Wh;
    const float* bias = (g == 0) ? bz : (g == 1) ? br : bh;
    float*       out  = (g == 0) ? g_xz : (g == 1) ? g_xr : g_xh;

    const int m0 = blockIdx.x * 128;
    const int n0 = blockIdx.y * 128;
    const int tid = (int)threadIdx.x;

    const int tx = tid & 15;
    const int ty = tid >> 4;

    const int arow = tid >> 1, aseg = tid & 1;
    const int brow = tid >> 5, bcol4 = (tid & 31) * 4;

    u64 acc2[8][4];
#pragma unroll
    for (int i = 0; i < 8; ++i)
#pragma unroll
        for (int j = 0; j < 4; ++j) acc2[i][j] = 0ull;

    for (int k0 = 0; k0 < I_; k0 += 8) {
        float4 av = *(const float4*)&xs[(size_t)(m0 + arow) * I_ + k0 + aseg * 4];
        float4 bv = *(const float4*)&W[(size_t)(k0 + brow) * H_ + n0 + bcol4];
        __syncthreads();
        As[(aseg * 4 + 0) * 132 + arow] = av.x;
        As[(aseg * 4 + 1) * 132 + arow] = av.y;
        As[(aseg * 4 + 2) * 132 + arow] = av.z;
        As[(aseg * 4 + 3) * 132 + arow] = av.w;
        *(float4*)&Bs[brow * 132 + bcol4] = bv;
        __syncthreads();
#pragma unroll
        for (int kk = 0; kk < 8; ++kk) {
            float a[8];
            float4 a0 = *(const float4*)&As[kk * 132 + ty * 8];
            float4 a1 = *(const float4*)&As[kk * 132 + ty * 8 + 4];
            ulonglong2 bq0 = *(const ulonglong2*)&Bs[kk * 132 + tx * 8];
            ulonglong2 bq1 = *(const ulonglong2*)&Bs[kk * 132 + tx * 8 + 4];
            a[0]=a0.x; a[1]=a0.y; a[2]=a0.z; a[3]=a0.w;
            a[4]=a1.x; a[5]=a1.y; a[6]=a1.z; a[7]=a1.w;
            u64 bp[4] = { bq0.x, bq0.y, bq1.x, bq1.y };
#pragma unroll
            for (int i = 0; i < 8; ++i) {
                u64 ap = pack2(a[i], a[i]);
#pragma unroll
                for (int j = 0; j < 4; ++j) acc2[i][j] = fma2(ap, bp[j], acc2[i][j]);
            }
        }
    }

#pragma unroll
    for (int j = 0; j < 4; ++j) {
        const int n = n0 + tx * 8 + 2 * j;
        const float bi0 = bias[n], bi1 = bias[n + 1];
#pragma unroll
        for (int i = 0; i < 8; ++i) {
            const int m = m0 + ty * 8 + i;
            const int t = m & (T_ - 1);
            const int b = m >> 10;
            float2 v = unpack2(acc2[i][j]);
            out[(size_t)(t * H_ + n) * B_ + b]     = v.x + bi0;
            out[(size_t)(t * H_ + n + 1) * B_ + b] = v.y + bi1;
        }
    }
}

// =================================================================================
// Persistent recurrence kernel: 128 CTAs (4 batch-groups x 32 col-groups), 1/SM,
// 512 threads (16 warps, 4/SMSP). CTA owns 16 batches x 16 h-columns.
// h stored DUPLICATED in smem: h_dup[bl*HD_S + 2k] = h_dup[..+2k+1] = h_k,
// so FMA-loop operand prep is a single LDS.64 per (b,k) — no pack MOVs.
// =================================================================================
#define NB_CTA 16
#define NC_CTA 16
#define HD_S 1040              // dup stride: 1024 + 16 pad
#define WS_S 52                // w_s[k*52 + c]; 16B aligned
#define SMEM_FLOATS (NB_CTA * HD_S + H_ * WS_S + 256 + 256)
#define SMEM_BYTES  (SMEM_FLOATS * 4)

__device__ __forceinline__ float sigmoidf_(float x) {
    return 1.0f / (1.0f + expf(-x));
}

// exchange-and-specialize butterfly stage on packed u64 accumulators.
#define RSTAGE64(arr, N, M, lane)                                            \
    {                                                                        \
        const bool hi_ = ((lane) & (M)) != 0;                                \
        _Pragma("unroll")                                                    \
        for (int i_ = 0; i_ < (N); ++i_) {                                   \
            u64 send_ = hi_ ? arr[i_] : arr[i_ + (N)];                       \
            u64 recv_ = __shfl_xor_sync(0xffffffffu, send_, (M));            \
            u64 keep_ = hi_ ? arr[i_ + (N)] : arr[i_];                       \
            arr[i_] = add2(keep_, recv_);                                    \
        }                                                                    \
    }

// Stage 16-batch slice into duplicated layout: 2048 float4 in, 4 per thread,
// each expanded to two interleaved-dup float4s.
__device__ __forceinline__ void stage_dup_(float* h_dup, const float4* __restrict__ src, int tid) {
    float4 v[4];
#pragma unroll
    for (int u = 0; u < 4; ++u)
        v[u] = __ldcg(src + tid + u * 512);
#pragma unroll
    for (int u = 0; u < 4; ++u) {
        const int i = tid + u * 512;
        const int bl = i >> 7;
        const int k4 = (i & 127) << 2;
        float* d = &h_dup[bl * HD_S + 2 * k4];
        *(float4*)d       = make_float4(v[u].x, v[u].x, v[u].y, v[u].y);
        *(float4*)(d + 4) = make_float4(v[u].z, v[u].z, v[u].w, v[u].w);
    }
}

__global__ __launch_bounds__(512, 1) void gru_rec_kernel(
    const float* __restrict__ Wz, const float* __restrict__ Wr, const float* __restrict__ Wh,
    float* __restrict__ out)
{
    extern __shared__ float smem[];
    float* h_dup = smem;                        // NB_CTA * 1040
    float* w_s   = h_dup + NB_CTA * HD_S;       // H_ * 52
    float* z_s   = w_s + H_ * WS_S;             // 16 x 16
    float* hk_s  = z_s + 256;                   // 16 x 16

    const int tid  = (int)threadIdx.x;
    const int w    = tid >> 5;
    const int lane = tid & 31;
    const int bg   = (int)blockIdx.x >> 5;
    const int cg   = (int)blockIdx.x & 31;
    const int col0 = cg * NC_CTA;
    const int bc0  = bg * NB_CTA;

    const int bh2 = w >> 3;                     // batch oct 0..1
    const int cq  = w & 7;                      // col quad 0..7
    const int blbase = bh2 * 8;

    // ---- one-time: stage 48 weight columns (16 z | 16 r | 16 h), slots 0..47 ----
    for (int i = tid; i < H_ * 48; i += 512) {
        const int k = i / 48, c = i % 48;
        const float* W = (c < 16) ? Wz : (c < 32) ? Wr : Wh;
        w_s[k * WS_S + c] = W[(size_t)(I_ + k) * H_ + col0 + (c & 15)];
    }

    // ---- per-lane epilogue mappings ----
    // phase A: 16 accs idx = cp*8+b; stages M=16,8,4,2 -> lane l: cp=(l>>4)&1,
    //          b=(l>>1)&7; final mask-1 add merges k-parity; col parity = l&1.
    const int cpA  = (lane >> 4) & 1;
    const int bA   = (lane >> 1) & 7;
    const int parA = lane & 1;
    const int gcA  = 4 * cq + 2 * cpA + parA;   // gate col 0..31 (0-15 z, 16-31 r)
    const bool isZ = gcA < 16;
    const int jA   = gcA & 15;
    const int blA  = blbase + bA;
    const float* xpA_base = isZ ? g_xz : g_xr;
    // phase B: 8 accs idx = b; stages M=16,8,4 -> lane l: b=(l>>2)&7; merges
    //          mask 2, mask 1; col parity = l&1; lanes with bit1 set duplicate.
    const int bB   = (lane >> 2) & 7;
    const int parB = lane & 1;
    const int jB   = 2 * cq + parB;
    const int blB  = blbase + bB;
    const bool actB = (lane & 2) == 0;

#pragma unroll 1
    for (int t = 0; t < T_; ++t) {
        // ---- stage h slice (duplicated layout); t==0: h = 0 ----
        __syncthreads();   // h_dup free (covers w_s staging on iter 0)
        if (t == 0) {
#pragma unroll
            for (int u = 0; u < 4; ++u) {
                const int i = tid + u * 512;
                const int bl = i >> 7, k4 = (i & 127) << 2;
                float* d = &h_dup[bl * HD_S + 2 * k4];
                *(float4*)d       = make_float4(0.f, 0.f, 0.f, 0.f);
                *(float4*)(d + 4) = make_float4(0.f, 0.f, 0.f, 0.f);
            }
        } else {
            stage_dup_(h_dup, (const float4*)&g_h[t & 1][(size_t)bc0 * H_], tid);
        }
        float xpA = __ldcg(&xpA_base[((size_t)t * H_ + col0 + jA) * B_ + bc0 + blA]);
        __syncthreads();

        // ---- phase A: z,r dots; warp = 2 col-pairs x 8 batches, k-split 32 ----
        u64 acc2[16];                          // idx = cp*8 + b
#pragma unroll
        for (int i = 0; i < 16; ++i) acc2[i] = 0ull;
#pragma unroll 4
        for (int it = 0; it < 16; ++it) {
            const int k = lane + (it << 5);
            ulonglong2 wq = *(const ulonglong2*)&w_s[k * WS_S + 4 * cq];
            u64 hq[8];
#pragma unroll
            for (int b = 0; b < 8; ++b)
                hq[b] = *(const u64*)&h_dup[(blbase + b) * HD_S + 2 * k];
#pragma unroll
            for (int b = 0; b < 8; ++b) {
                acc2[b]     = fma2(wq.x, hq[b], acc2[b]);
                acc2[8 + b] = fma2(wq.y, hq[b], acc2[8 + b]);
            }
        }
        RSTAGE64(acc2, 8, 16, lane)
        RSTAGE64(acc2, 4,  8, lane)
        RSTAGE64(acc2, 2,  4, lane)
        RSTAGE64(acc2, 1,  2, lane)
        acc2[0] = add2(acc2[0], __shfl_xor_sync(0xffffffffu, acc2[0], 1));

        {
            float2 d = unpack2(acc2[0]);
            const float dot = parA ? d.y : d.x;
            if (isZ) {
                z_s[blA * 16 + jA] = sigmoidf_(xpA + dot);
            } else {
                const float r    = sigmoidf_(xpA + dot);
                const float hold = h_dup[blA * HD_S + 2 * (col0 + jA)];
                hk_s[blA * 16 + jA] = hold;
                __stcg(&g_rh[(size_t)(bc0 + blA) * H_ + col0 + jA], r * hold);
            }
        }
        // prefetch phase-B gate operand (independent of rh exchange)
        float xpB = __ldcg(&g_xh[((size_t)t * H_ + col0 + jB) * B_ + bc0 + blB]);
        group_sync_(bg);

        // ---- stage r*h slice ----
        stage_dup_(h_dup, (const float4*)&g_rh[(size_t)bc0 * H_], tid);
        __syncthreads();

        // ---- phase B: candidate dots; warp = 1 col-pair x 8 batches ----
        u64 acc2B[8];                          // idx = b
#pragma unroll
        for (int i = 0; i < 8; ++i) acc2B[i] = 0ull;
#pragma unroll 4
        for (int it = 0; it < 16; ++it) {
            const int k = lane + (it << 5);
            const u64 wq = *(const u64*)&w_s[k * WS_S + 32 + 2 * cq];
            u64 hq[8];
#pragma unroll
            for (int b = 0; b < 8; ++b)
                hq[b] = *(const u64*)&h_dup[(blbase + b) * HD_S + 2 * k];
#pragma unroll
            for (int b = 0; b < 8; ++b)
                acc2B[b] = fma2(wq, hq[b], acc2B[b]);
        }
        RSTAGE64(acc2B, 4, 16, lane)
        RSTAGE64(acc2B, 2,  8, lane)
        RSTAGE64(acc2B, 1,  4, lane)
        acc2B[0] = add2(acc2B[0], __shfl_xor_sync(0xffffffffu, acc2B[0], 2));
        acc2B[0] = add2(acc2B[0], __shfl_xor_sync(0xffffffffu, acc2B[0], 1));

        if (actB) {
            float2 pr = unpack2(acc2B[0]);
            const float cand = parB ? pr.y : pr.x;
            const float z    = z_s[blB * 16 + jB];
            const float hold = hk_s[blB * 16 + jB];
            const float ht = tanhf(xpB + cand);
            const float hn = fmaf(z, ht - hold, hold);
            const int gb = bc0 + blB;
            out[(size_t)gb * T_ * H_ + (size_t)t * H_ + col0 + jB] = hn;
            __stcg(&g_h[(t + 1) & 1][(size_t)gb * H_ + col0 + jB], hn);
            if (t == T_ - 1)
                out[(size_t)B_ * T_ * H_ + (size_t)gb * H_ + col0 + jB] = hn;
        }
        group_sync_(bg);
    }
}

// =================================================================================
extern "C" void kernel_launch(void* const* d_in, const int* in_sizes, int n_in,
                              void* d_out, int out_size) {
    const float* xs = (const float*)d_in[0];
    const float* Wz = (const float*)d_in[1];
    const float* bz = (const float*)d_in[2];
    const float* Wr = (const float*)d_in[3];
    const float* br = (const float*)d_in[4];
    const float* Wh = (const float*)d_in[5];
    const float* bh = (const float*)d_in[6];
    float* out = (float*)d_out;

    cudaFuncSetAttribute(gru_rec_kernel,
                         cudaFuncAttributeMaxDynamicSharedMemorySize, SMEM_BYTES);

    dim3 pg(T_ * B_ / 128, H_ / 128, 3);
    gru_proj_kernel<<<pg, 256>>>(xs, Wz, Wr, Wh, bz, br, bh);

    gru_rec_kernel<<<128, 512, SMEM_BYTES>>>(Wz, Wr, Wh, out);
}

// round 11
// speedup vs baseline: 1.3572x; 1.3572x over previous
#include <cuda_runtime.h>
#include <cstdint>

#define B_ 64
#define T_ 1024
#define I_ 256
#define H_ 512

typedef unsigned long long u64;

// ---------------- packed f32x2 helpers (sm_103a) ----------------
__device__ __forceinline__ u64 pack2(float lo, float hi) {
    u64 r; asm("mov.b64 %0, {%1, %2};" : "=l"(r) : "f"(lo), "f"(hi)); return r;
}
__device__ __forceinline__ u64 fma2(u64 a, u64 b, u64 c) {
    u64 d; asm("fma.rn.f32x2 %0, %1, %2, %3;" : "=l"(d) : "l"(a), "l"(b), "l"(c)); return d;
}
__device__ __forceinline__ u64 add2(u64 a, u64 b) {
    u64 d; asm("add.rn.f32x2 %0, %1, %2;" : "=l"(d) : "l"(a), "l"(b)); return d;
}
__device__ __forceinline__ float2 unpack2(u64 v) {
    float2 r; asm("mov.b64 {%0, %1}, %2;" : "=f"(r.x), "=f"(r.y) : "l"(v)); return r;
}

// ---------------- static device scratch ----------------
// Projections stored transposed: [t][j][b]  -> index (t*H_ + j)*B_ + b
__device__ float g_xz[(size_t)T_ * H_ * B_];
__device__ float g_xr[(size_t)T_ * H_ * B_];
__device__ float g_xh[(size_t)T_ * H_ * B_];
// Hidden state double buffer + r*h exchange buffer, layout [b][j]
__device__ float g_h[2][B_ * H_];
__device__ float g_rh[B_ * H_];
// Per-batch-group barrier: 8 slots, 128B apart; zero-init; gen monotone (replay-safe).
struct __align__(128) BarSlot { unsigned count; unsigned gen; unsigned pad[30]; };
__device__ BarSlot g_bar[8];

// ---------------- per-batch-group barrier (16 CTAs), release/acquire ----------
__device__ __forceinline__ void group_sync_(int bg) {
    __syncthreads();
    if (threadIdx.x == 0) {
        unsigned* cnt  = &g_bar[bg].count;
        unsigned* genp = &g_bar[bg].gen;
        unsigned g0, old, v;
        asm volatile("ld.acquire.gpu.u32 %0, [%1];" : "=r"(g0) : "l"(genp) : "memory");
        asm volatile("atom.release.gpu.add.u32 %0, [%1], %2;"
                     : "=r"(old) : "l"(cnt), "r"(1u) : "memory");
        if (old == 15u) {
            asm volatile("st.relaxed.gpu.u32 [%0], %1;" :: "l"(cnt), "r"(0u) : "memory");
            asm volatile("st.release.gpu.u32 [%0], %1;" :: "l"(genp), "r"(g0 + 1u) : "memory");
        } else {
            do {
                asm volatile("ld.acquire.gpu.u32 %0, [%1];" : "=r"(v) : "l"(genp) : "memory");
            } while (v == g0);
        }
    }
    __syncthreads();
}

// =================================================================================
// Projection GEMM (unchanged; proven)
// =================================================================================
__global__ __launch_bounds__(256) void gru_proj_kernel(
    const float* __restrict__ xs,
    const float* __restrict__ Wz, const float* __restrict__ Wr, const float* __restrict__ Wh,
    const float* __restrict__ bz, const float* __restrict__ br, const float* __restrict__ bh)
{
    __shared__ float As[8 * 132];
    __shared__ float Bs[8 * 132];

    const int g = blockIdx.z;
    const float* W    = (g == 0) ? Wz : (g == 1) ? Wr : Wh;
    const float* bias = (g == 0) ? bz : (g == 1) ? br : bh;
    float*       out  = (g == 0) ? g_xz : (g == 1) ? g_xr : g_xh;

    const int m0 = blockIdx.x * 128;
    const int n0 = blockIdx.y * 128;
    const int tid = (int)threadIdx.x;

    const int tx = tid & 15;
    const int ty = tid >> 4;

    const int arow = tid >> 1, aseg = tid & 1;
    const int brow = tid >> 5, bcol4 = (tid & 31) * 4;

    u64 acc2[8][4];
#pragma unroll
    for (int i = 0; i < 8; ++i)
#pragma unroll
        for (int j = 0; j < 4; ++j) acc2[i][j] = 0ull;

    for (int k0 = 0; k0 < I_; k0 += 8) {
        float4 av = *(const float4*)&xs[(size_t)(m0 + arow) * I_ + k0 + aseg * 4];
        float4 bv = *(const float4*)&W[(size_t)(k0 + brow) * H_ + n0 + bcol4];
        __syncthreads();
        As[(aseg * 4 + 0) * 132 + arow] = av.x;
        As[(aseg * 4 + 1) * 132 + arow] = av.y;
        As[(aseg * 4 + 2) * 132 + arow] = av.z;
        As[(aseg * 4 + 3) * 132 + arow] = av.w;
        *(float4*)&Bs[brow * 132 + bcol4] = bv;
        __syncthreads();
#pragma unroll
        for (int kk = 0; kk < 8; ++kk) {
            float a[8];
            float4 a0 = *(const float4*)&As[kk * 132 + ty * 8];
            float4 a1 = *(const float4*)&As[kk * 132 + ty * 8 + 4];
            ulonglong2 bq0 = *(const ulonglong2*)&Bs[kk * 132 + tx * 8];
            ulonglong2 bq1 = *(const ulonglong2*)&Bs[kk * 132 + tx * 8 + 4];
            a[0]=a0.x; a[1]=a0.y; a[2]=a0.z; a[3]=a0.w;
            a[4]=a1.x; a[5]=a1.y; a[6]=a1.z; a[7]=a1.w;
            u64 bp[4] = { bq0.x, bq0.y, bq1.x, bq1.y };
#pragma unroll
            for (int i = 0; i < 8; ++i) {
                u64 ap = pack2(a[i], a[i]);
#pragma unroll
                for (int j = 0; j < 4; ++j) acc2[i][j] = fma2(ap, bp[j], acc2[i][j]);
            }
        }
    }

#pragma unroll
    for (int j = 0; j < 4; ++j) {
        const int n = n0 + tx * 8 + 2 * j;
        const float bi0 = bias[n], bi1 = bias[n + 1];
#pragma unroll
        for (int i = 0; i < 8; ++i) {
            const int m = m0 + ty * 8 + i;
            const int t = m & (T_ - 1);
            const int b = m >> 10;
            float2 v = unpack2(acc2[i][j]);
            out[(size_t)(t * H_ + n) * B_ + b]     = v.x + bi0;
            out[(size_t)(t * H_ + n + 1) * B_ + b] = v.y + bi1;
        }
    }
}

// =================================================================================
// Persistent recurrence: 128 CTAs = 8 batch-groups x 16 col-groups, 256 thr, 1/SM.
// CTA (bg, cg) owns batches [bg*8, bg*8+8) and h-columns [cg*32, cg*32+32).
// Per-warp compute shape identical to the proven round-8 kernel.
// =================================================================================
#define NB_CTA 8               // batches per CTA
#define NC_CTA 32              // h-columns per CTA (96 gate-cols z|r|cand)
#define HS_S 520               // h_s[bl*520 + k]; load bank = (8b + lane)&31
#define WS_S 100               // w_s[k*100 + c], c 0..95; 16B aligned, quad 25k+c/4
#define ZS_S 33                // z_s/hk_s stride (kills 8-way STS conflict)
#define SMEM_FLOATS (NB_CTA * HS_S + H_ * WS_S + NB_CTA * ZS_S * 2)
#define SMEM_BYTES  (SMEM_FLOATS * 4)

__device__ __forceinline__ float sigmoidf_(float x) {
    return 1.0f / (1.0f + expf(-x));
}

// exchange-and-specialize butterfly stage on packed u64 accumulators.
#define RSTAGE64(arr, N, M, lane)                                            \
    {                                                                        \
        const bool hi_ = ((lane) & (M)) != 0;                                \
        _Pragma("unroll")                                                    \
        for (int i_ = 0; i_ < (N); ++i_) {                                   \
            u64 send_ = hi_ ? arr[i_] : arr[i_ + (N)];                       \
            u64 recv_ = __shfl_xor_sync(0xffffffffu, send_, (M));            \
            u64 keep_ = hi_ ? arr[i_ + (N)] : arr[i_];                       \
            arr[i_] = add2(keep_, recv_);                                    \
        }                                                                    \
    }

// Stage this CTA's 8-batch slice: 1024 float4, 4 per thread, LDG-batched.
__device__ __forceinline__ void stage_h_(float* h_s, const float4* __restrict__ src, int tid) {
    float4 v[4];
#pragma unroll
    for (int u = 0; u < 4; ++u)
        v[u] = __ldcg(src + tid + u * 256);
#pragma unroll
    for (int u = 0; u < 4; ++u) {
        const int i = tid + u * 256;
        const int bl = i >> 7;               // 128 float4 per batch row
        const int k4 = (i & 127) << 2;
        *(float4*)&h_s[bl * HS_S + k4] = v[u];
    }
}

__global__ __launch_bounds__(256, 1) void gru_rec_kernel(
    const float* __restrict__ Wz, const float* __restrict__ Wr, const float* __restrict__ Wh,
    float* __restrict__ out)
{
    extern __shared__ float smem[];
    float* h_s  = smem;                        // NB_CTA * 520
    float* w_s  = h_s + NB_CTA * HS_S;         // H_ * 100
    float* z_s  = w_s + H_ * WS_S;             // 8 x 33
    float* hk_s = z_s + NB_CTA * ZS_S;         // 8 x 33

    const int tid  = (int)threadIdx.x;
    const int w    = tid >> 5;
    const int lane = tid & 31;
    const int bg   = (int)blockIdx.x >> 4;     // batch group 0..7
    const int cg   = (int)blockIdx.x & 15;     // col group 0..15
    const int col0 = cg * NC_CTA;
    const int bc0  = bg * NB_CTA;

    // ---- one-time: stage 96 weight columns (32 z | 32 r | 32 cand) ----
    for (int i = tid; i < H_ * 96; i += 256) {
        const int k = i / 96, c = i % 96;
        const float* W = (c < 32) ? Wz : (c < 64) ? Wr : Wh;
        w_s[k * WS_S + c] = W[(size_t)(I_ + k) * H_ + col0 + (c & 31)];
    }

    // ---- per-lane epilogue mappings (clone of round-8 trees) ----
    // phase A: warp w owns gate-col slots [8w, 8w+8) (w<4: z cols, w>=4: r cols).
    // 32 accs idx = cp*8+b; 5-stage cascade -> lane l holds idx l: cp=l>>3, b=l&7.
    const int sA   = 8 * w;                    // weight slot base (z/r region)
    const int cpA  = lane >> 3;
    const int bA   = lane & 7;
    const int jA0  = (sA + 2 * cpA) & 31;      // local h-col (even), pair jA0, jA0+1
    const int blA  = bA;
    const bool isZ = w < 4;
    const float* xpA_base = isZ ? g_xz : g_xr;
    // phase B: warp w owns cand cols [4w, 4w+4) at slots 64+4w.
    // 16 accs idx = cp*8+b; 4-stage cascade -> lane l holds idx (l>>1)&15:
    // cp=(l>>4)&1, b=(l>>1)&7; final mask-1 add; parity l&1 = column.
    const int blB = (lane >> 1) & 7;
    const int jB  = 4 * w + 2 * ((lane >> 4) & 1) + (lane & 1);

#pragma unroll 1
    for (int t = 0; t < T_; ++t) {
        // ---- stage h slice (layout [local b][k]); t==0: h = 0 ----
        __syncthreads();   // h_s free (covers w_s staging on iter 0)
        if (t == 0) {
#pragma unroll
            for (int u = 0; u < 4; ++u) {
                const int i = tid + u * 256;
                const int bl = i >> 7, k4 = (i & 127) << 2;
                *(float4*)&h_s[bl * HS_S + k4] = make_float4(0.f, 0.f, 0.f, 0.f);
            }
        } else {
            stage_h_(h_s, (const float4*)&g_h[t & 1][(size_t)bc0 * H_], tid);
        }
        const size_t xiA = ((size_t)t * H_ + col0 + jA0) * B_ + bc0 + blA;
        float xpA0 = __ldcg(&xpA_base[xiA]);
        float xpA1 = __ldcg(&xpA_base[xiA + B_]);
        __syncthreads();

        // ---- phase A: z,r dots; warp = 4 col-pairs x 8 batches, k-split 32 ----
        u64 acc2[32];                          // idx = cp*8 + b
#pragma unroll
        for (int i = 0; i < 32; ++i) acc2[i] = 0ull;
#pragma unroll 4
        for (int it = 0; it < 16; ++it) {
            const int k = lane + (it << 5);
            ulonglong2 wq0 = *(const ulonglong2*)&w_s[k * WS_S + sA];
            ulonglong2 wq1 = *(const ulonglong2*)&w_s[k * WS_S + sA + 4];
            u64 wp[4] = { wq0.x, wq0.y, wq1.x, wq1.y };
            float hv[8];
#pragma unroll
            for (int b = 0; b < 8; ++b) hv[b] = h_s[b * HS_S + k];
            u64 hb[8];
#pragma unroll
            for (int b = 0; b < 8; ++b) hb[b] = pack2(hv[b], hv[b]);
#pragma unroll
            for (int cp = 0; cp < 4; ++cp)
#pragma unroll
                for (int b = 0; b < 8; ++b)
                    acc2[cp * 8 + b] = fma2(wp[cp], hb[b], acc2[cp * 8 + b]);
        }
        RSTAGE64(acc2, 16, 16, lane)
        RSTAGE64(acc2,  8,  8, lane)
        RSTAGE64(acc2,  4,  4, lane)
        RSTAGE64(acc2,  2,  2, lane)
        RSTAGE64(acc2,  1,  1, lane)

        {
            float2 dot = unpack2(acc2[0]);     // cols (jA0, jA0+1), batch blA
            if (isZ) {
                z_s[blA * ZS_S + jA0]     = sigmoidf_(xpA0 + dot.x);
                z_s[blA * ZS_S + jA0 + 1] = sigmoidf_(xpA1 + dot.y);
            } else {
                const float r0 = sigmoidf_(xpA0 + dot.x);
                const float r1 = sigmoidf_(xpA1 + dot.y);
                const float h0 = h_s[blA * HS_S + col0 + jA0];
                const float h1 = h_s[blA * HS_S + col0 + jA0 + 1];
                hk_s[blA * ZS_S + jA0]     = h0;
                hk_s[blA * ZS_S + jA0 + 1] = h1;
                float2 rh2 = make_float2(r0 * h0, r1 * h1);
                __stcg((float2*)&g_rh[(size_t)(bc0 + blA) * H_ + col0 + jA0], rh2);
            }
        }
        // prefetch phase-B gate operand (independent of rh exchange)
        float xpB = __ldcg(&g_xh[((size_t)t * H_ + col0 + jB) * B_ + bc0 + blB]);
        group_sync_(bg);

        // ---- stage r*h slice ----
        stage_h_(h_s, (const float4*)&g_rh[(size_t)bc0 * H_], tid);
        __syncthreads();

        // ---- phase B: candidate dots; warp = 2 col-pairs x 8 batches ----
        u64 acc2B[16];                         // idx = cp*8 + b
#pragma unroll
        for (int i = 0; i < 16; ++i) acc2B[i] = 0ull;
#pragma unroll 4
        for (int it = 0; it < 16; ++it) {
            const int k = lane + (it << 5);
            ulonglong2 wq = *(const ulonglong2*)&w_s[k * WS_S + 64 + 4 * w];
            u64 wp[2] = { wq.x, wq.y };
            float hv[8];
#pragma unroll
            for (int b = 0; b < 8; ++b) hv[b] = h_s[b * HS_S + k];
            u64 hb[8];
#pragma unroll
            for (int b = 0; b < 8; ++b) hb[b] = pack2(hv[b], hv[b]);
#pragma unroll
            for (int cp = 0; cp < 2; ++cp)
#pragma unroll
                for (int b = 0; b < 8; ++b)
                    acc2B[cp * 8 + b] = fma2(wp[cp], hb[b], acc2B[cp * 8 + b]);
        }
        RSTAGE64(acc2B, 8, 16, lane)
        RSTAGE64(acc2B, 4,  8, lane)
        RSTAGE64(acc2B, 2,  4, lane)
        RSTAGE64(acc2B, 1,  2, lane)
        acc2B[0] = add2(acc2B[0], __shfl_xor_sync(0xffffffffu, acc2B[0], 1));

        {
            float2 pair = unpack2(acc2B[0]);
            const float cand = (lane & 1) ? pair.y : pair.x;
            const float z    = z_s[blB * ZS_S + jB];
            const float hold = hk_s[blB * ZS_S + jB];
            const float ht = tanhf(xpB + cand);
            const float hn = fmaf(z, ht - hold, hold);
            const int gb = bc0 + blB;
            out[(size_t)gb * T_ * H_ + (size_t)t * H_ + col0 + jB] = hn;
            __stcg(&g_h[(t + 1) & 1][(size_t)gb * H_ + col0 + jB], hn);
            if (t == T_ - 1)
                out[(size_t)B_ * T_ * H_ + (size_t)gb * H_ + col0 + jB] = hn;
        }
        group_sync_(bg);
    }
}

// =================================================================================
extern "C" void kernel_launch(void* const* d_in, const int* in_sizes, int n_in,
                              void* d_out, int out_size) {
    const float* xs = (const float*)d_in[0];
    const float* Wz = (const float*)d_in[1];
    const float* bz = (const float*)d_in[2];
    const float* Wr = (const float*)d_in[3];
    const float* br = (const float*)d_in[4];
    const float* Wh = (const float*)d_in[5];
    const float* bh = (const float*)d_in[6];
    float* out = (float*)d_out;

    cudaFuncSetAttribute(gru_rec_kernel,
                         cudaFuncAttributeMaxDynamicSharedMemorySize, SMEM_BYTES);

    dim3 pg(T_ * B_ / 128, H_ / 128, 3);
    gru_proj_kernel<<<pg, 256>>>(xs, Wz, Wr, Wh, bz, br, bh);

    gru_rec_kernel<<<128, 256, SMEM_BYTES>>>(Wz, Wr, Wh, out);
}